// round 12
// baseline (speedup 1.0000x reference)
#include <cuda_runtime.h>
#include <cuda_bf16.h>

// Forward-fill (LOCF) over x:(B=32, L=4096, N=256) fp32, NaN = missing.
// Single kernel, no auxiliary state: threads needing a carry walk backward
// through x itself (E[walk] = 1.25 loads; P(walk > k) = 0.2^k, L2-likely).
//
//   chunk = 64 steps; grid = B*(L/64) = 2048 CTAs x 128 threads.
//   thread = channel pair (float2): 64 front-batched LDG.64 -> 512B in
//   flight per thread (~196 KB/SM), contiguous 64KB blocks per CTA stream.
//   Phase 1: batch-load 64 steps into regs.
//   Phase 2: combined scan + store (register-fed; prefix gets NaN).
//   Phase 3: ~20% of channels: walk x backwards for the carry, patch prefix.

#define BB 32
#define LL 4096
#define NN 256
#define LC 64
#define CC (LL / LC)          // 64 chunks per batch
#define NCHUNK (BB * CC)      // 2048 CTAs
#define N2 (NN / 2)           // 128 float2 channels -> block size

// Backward walk: last observation in this channel at step <= l0. 0.0f if none.
static __device__ __forceinline__ float walk_back(const float* __restrict__ xrow,
                                                  int l0) {
    for (int l = l0; l >= 0; l--) {
        float v = __ldg(xrow + (size_t)l * NN);
        if (v == v) return v;
    }
    return 0.0f;
}

template <bool WRITE_MASK>
__global__ void __launch_bounds__(128) k_locf(const float2* __restrict__ x,
                                              float2* __restrict__ out,
                                              float2* __restrict__ outm) {
    const int t   = threadIdx.x;          // channel pair (channels 2t, 2t+1)
    const int bid = blockIdx.x;           // (b, c)
    const int c   = bid % CC;
    const int b   = bid / CC;

    const size_t base = ((size_t)b * LL + (size_t)c * LC) * N2 + t;

    // ---- phase 1: 64 independent LDG.64 (512 bytes in flight per thread)
    float2 v[LC];
    #pragma unroll
    for (int l = 0; l < LC; l++)
        v[l] = __ldcs(x + base + (size_t)l * N2);

    // ---- phase 2: combined scan + store (register-fed stores; prefix = NaN)
    float sx = __int_as_float(0x7fc00000), sy = sx;
    int fx = 0, fy = 0;
    #pragma unroll
    for (int l = 0; l < LC; l++) {
        bool vx = (v[l].x == v[l].x), vy = (v[l].y == v[l].y);
        sx = vx ? v[l].x : sx;
        sy = vy ? v[l].y : sy;
        fx = (sx == sx) ? fx : (l + 1);
        fy = (sy == sy) ? fy : (l + 1);
        __stcs(out + base + (size_t)l * N2, make_float2(sx, sy));
        if (WRITE_MASK)
            __stcs(outm + base + (size_t)l * N2,
                   make_float2(vx ? 1.0f : 0.0f, vy ? 1.0f : 0.0f));
    }

    // ---- phase 3: carry via backward walk through x, then patch the prefix
    if (fx > 0 || fy > 0) {
        float cx = 0.0f, cy = 0.0f;
        if (c > 0) {
            const float* xs = (const float*)x + (size_t)b * LL * NN;
            const int l0 = c * LC - 1;
            if (fx > 0) cx = walk_back(xs + 2 * t, l0);
            if (fy > 0) cy = walk_back(xs + 2 * t + 1, l0);
        }
        float* o = (float*)out;
        const size_t sbase = 2 * base;    // scalar index of channel 2t
        for (int l = 0; l < fx; l++)
            __stcs(o + sbase + (size_t)l * NN, cx);
        for (int l = 0; l < fy; l++)
            __stcs(o + sbase + 1 + (size_t)l * NN, cy);
    }
}

extern "C" void kernel_launch(void* const* d_in, const int* in_sizes, int n_in,
                              void* d_out, int out_size) {
    const float2* x = (const float2*)d_in[0];
    long long total = (long long)in_sizes[0];   // 33554432
    float* out = (float*)d_out;

    if ((long long)out_size >= 2 * total) {
        k_locf<true><<<NCHUNK, N2>>>(x, (float2*)out, (float2*)(out + total));
    } else {
        k_locf<false><<<NCHUNK, N2>>>(x, (float2*)out, nullptr);
    }
}

// round 13
// speedup vs baseline: 1.0136x; 1.0136x over previous
#include <cuda_runtime.h>
#include <cuda_bf16.h>

// Forward-fill (LOCF) over x:(B=32, L=4096, N=256) fp32, NaN = missing.
// Single kernel, no auxiliary state: threads needing a carry walk backward
// through x itself (E[walk] = 1.25 loads; P(walk > k) = 0.2^k, L2-likely).
//
//   chunk = 32 steps; grid = B*(L/32) = 4096 CTAs x 64 threads.
//   thread = 4 channels (float4): 32 front-batched LDG.128 -> 512B in flight
//   per thread; STG.128 stores (lower issue cost than 2x STG.64).
//   Phase 1: batch-load 32 steps into regs.
//   Phase 2: combined scan + store (register-fed; prefix gets NaN).
//   Phase 3: channels with unresolved prefix walk x backwards, patch prefix.

#define BB 32
#define LL 4096
#define NN 256
#define LC 32
#define CC (LL / LC)          // 128 chunks per batch
#define NCHUNK (BB * CC)      // 4096 CTAs
#define N4 (NN / 4)           // 64 float4 groups -> block size

// Backward walk: last observation in this channel at step <= l0. 0.0f if none.
static __device__ __forceinline__ float walk_back(const float* __restrict__ xrow,
                                                  int l0) {
    for (int l = l0; l >= 0; l--) {
        float v = __ldg(xrow + (size_t)l * NN);
        if (v == v) return v;
    }
    return 0.0f;
}

template <bool WRITE_MASK>
__global__ void __launch_bounds__(64) k_locf(const float4* __restrict__ x,
                                             float4* __restrict__ out,
                                             float4* __restrict__ outm) {
    const int t   = threadIdx.x;          // float4 channel group (4t..4t+3)
    const int bid = blockIdx.x;           // (b, c)
    const int c   = bid % CC;
    const int b   = bid / CC;

    const size_t base = ((size_t)b * LL + (size_t)c * LC) * N4 + t;

    // ---- phase 1: 32 independent LDG.128 (512 bytes in flight per thread)
    float4 v[LC];
    #pragma unroll
    for (int l = 0; l < LC; l++)
        v[l] = __ldcs(x + base + (size_t)l * N4);

    // ---- phase 2: combined scan + store (register-fed stores; prefix = NaN)
    const float qnan = __int_as_float(0x7fc00000);
    float sx = qnan, sy = qnan, sz = qnan, sw = qnan;
    int fx = 0, fy = 0, fz = 0, fw = 0;
    #pragma unroll
    for (int l = 0; l < LC; l++) {
        bool vx = (v[l].x == v[l].x), vy = (v[l].y == v[l].y);
        bool vz = (v[l].z == v[l].z), vw = (v[l].w == v[l].w);
        sx = vx ? v[l].x : sx;  sy = vy ? v[l].y : sy;
        sz = vz ? v[l].z : sz;  sw = vw ? v[l].w : sw;
        fx = (sx == sx) ? fx : (l + 1);  fy = (sy == sy) ? fy : (l + 1);
        fz = (sz == sz) ? fz : (l + 1);  fw = (sw == sw) ? fw : (l + 1);
        __stcs(out + base + (size_t)l * N4, make_float4(sx, sy, sz, sw));
        if (WRITE_MASK)
            __stcs(outm + base + (size_t)l * N4,
                   make_float4(vx ? 1.0f : 0.0f, vy ? 1.0f : 0.0f,
                               vz ? 1.0f : 0.0f, vw ? 1.0f : 0.0f));
    }

    // ---- phase 3: carry via backward walk through x, then patch the prefix
    if ((fx | fy | fz | fw) != 0) {
        float cx = 0.0f, cy = 0.0f, cz = 0.0f, cw = 0.0f;
        if (c > 0) {
            const float* xs = (const float*)x + (size_t)b * LL * NN;
            const int l0 = c * LC - 1;
            if (fx > 0) cx = walk_back(xs + 4 * t + 0, l0);
            if (fy > 0) cy = walk_back(xs + 4 * t + 1, l0);
            if (fz > 0) cz = walk_back(xs + 4 * t + 2, l0);
            if (fw > 0) cw = walk_back(xs + 4 * t + 3, l0);
        }
        float* o = (float*)out;
        const size_t sbase = 4 * base;    // scalar index of channel 4t
        for (int l = 0; l < fx; l++) __stcs(o + sbase + 0 + (size_t)l * NN, cx);
        for (int l = 0; l < fy; l++) __stcs(o + sbase + 1 + (size_t)l * NN, cy);
        for (int l = 0; l < fz; l++) __stcs(o + sbase + 2 + (size_t)l * NN, cz);
        for (int l = 0; l < fw; l++) __stcs(o + sbase + 3 + (size_t)l * NN, cw);
    }
}

extern "C" void kernel_launch(void* const* d_in, const int* in_sizes, int n_in,
                              void* d_out, int out_size) {
    const float4* x = (const float4*)d_in[0];
    long long total = (long long)in_sizes[0];   // 33554432
    float* out = (float*)d_out;

    if ((long long)out_size >= 2 * total) {
        k_locf<true><<<NCHUNK, N4>>>(x, (float4*)out, (float4*)(out + total));
    } else {
        k_locf<false><<<NCHUNK, N4>>>(x, (float4*)out, nullptr);
    }
}

// round 14
// speedup vs baseline: 1.0418x; 1.0279x over previous
#include <cuda_runtime.h>
#include <cuda_bf16.h>

// Forward-fill (LOCF) over x:(B=32, L=4096, N=256) fp32, NaN = missing.
// Single kernel, NO auxiliary state: threads that need a carry walk backward
// through x itself (E[walk] = 1.25 loads; P(walk > k) = 0.2^k, L2-likely).
//
//   chunk = 32 steps; grid = B*(L/32) = 4096 CTAs x 128 threads.
//   thread = channel pair (float2): 32 front-batched LDG.64 (256B in flight).
//   Phase 1: batch-load 32 steps into regs.
//   Phase 2: combined scan + store (stores register-fed; prefix gets NaN).
//   Phase 3: ~20% of channels: walk x backwards for the carry, patch prefix.
//
// Measured (R11): 64.0 us total, main kernel 61.1 us @ 5.67 TB/s -- the
// achieved ceiling for this 1R:2W stream on GB300 at NAT clocks. LC in
// {16,64}, scalar/float4 widths, pub-array protocols, and serial-segment
// shapes all measured equal or worse (rounds 3-13).

#define BB 32
#define LL 4096
#define NN 256
#define LC 32
#define CC (LL / LC)          // 128 chunks per batch
#define NCHUNK (BB * CC)      // 4096 CTAs
#define N2 (NN / 2)           // 128 float2 channels -> block size

// Backward walk: last observation in this channel at step <= l0. 0.0f if none.
static __device__ __forceinline__ float walk_back(const float* __restrict__ xrow,
                                                  int l0) {
    for (int l = l0; l >= 0; l--) {
        float v = __ldg(xrow + (size_t)l * NN);
        if (v == v) return v;
    }
    return 0.0f;
}

template <bool WRITE_MASK>
__global__ void __launch_bounds__(128) k_locf(const float2* __restrict__ x,
                                              float2* __restrict__ out,
                                              float2* __restrict__ outm) {
    const int t   = threadIdx.x;          // channel pair (channels 2t, 2t+1)
    const int bid = blockIdx.x;           // (b, c)
    const int c   = bid % CC;
    const int b   = bid / CC;

    const size_t base = ((size_t)b * LL + (size_t)c * LC) * N2 + t;

    // ---- phase 1: 32 independent LDG.64 (256 bytes in flight per thread)
    float2 v[LC];
    #pragma unroll
    for (int l = 0; l < LC; l++)
        v[l] = __ldcs(x + base + (size_t)l * N2);

    // ---- phase 2: combined scan + store (register-fed stores; prefix = NaN)
    float sx = __int_as_float(0x7fc00000), sy = sx;
    int fx = 0, fy = 0;
    #pragma unroll
    for (int l = 0; l < LC; l++) {
        bool vx = (v[l].x == v[l].x), vy = (v[l].y == v[l].y);
        sx = vx ? v[l].x : sx;
        sy = vy ? v[l].y : sy;
        fx = (sx == sx) ? fx : (l + 1);
        fy = (sy == sy) ? fy : (l + 1);
        __stcs(out + base + (size_t)l * N2, make_float2(sx, sy));
        if (WRITE_MASK)
            __stcs(outm + base + (size_t)l * N2,
                   make_float2(vx ? 1.0f : 0.0f, vy ? 1.0f : 0.0f));
    }

    // ---- phase 3: carry via backward walk through x, then patch the prefix
    if (fx > 0 || fy > 0) {
        float cx = 0.0f, cy = 0.0f;
        if (c > 0) {
            const float* xs = (const float*)x + (size_t)b * LL * NN;
            const int l0 = c * LC - 1;
            if (fx > 0) cx = walk_back(xs + 2 * t, l0);
            if (fy > 0) cy = walk_back(xs + 2 * t + 1, l0);
        }
        float* o = (float*)out;
        const size_t sbase = 2 * base;    // scalar index of channel 2t
        for (int l = 0; l < fx; l++)
            __stcs(o + sbase + (size_t)l * NN, cx);
        for (int l = 0; l < fy; l++)
            __stcs(o + sbase + 1 + (size_t)l * NN, cy);
    }
}

extern "C" void kernel_launch(void* const* d_in, const int* in_sizes, int n_in,
                              void* d_out, int out_size) {
    const float2* x = (const float2*)d_in[0];
    long long total = (long long)in_sizes[0];   // 33554432
    float* out = (float*)d_out;

    if ((long long)out_size >= 2 * total) {
        k_locf<true><<<NCHUNK, N2>>>(x, (float2*)out, (float2*)(out + total));
    } else {
        k_locf<false><<<NCHUNK, N2>>>(x, (float2*)out, nullptr);
    }
}